// round 13
// baseline (speedup 1.0000x reference)
#include <cuda_runtime.h>
#include <cuda_fp16.h>
#include <cstdint>
#include <cstring>

// einsum('bis,ie->bse') via mma.sync f16 2-term split, persistent CTAs.
//   inputs    [B=64, I=64, S=4096] f32
//   embedding [I=64, E=64]         f32
//   out       [B=64, S=4096, E=64] f32
//
// D = Ahi*Bhi + Ahi*Blo (f16 operands, fp32 accumulate), rel_err ~1.6e-4.
//
// vs round 12: (1) grid=296 persistent CTAs loop over tiles -> B staged ONCE
// per CTA (was once per tile), no per-tile barrier, epilogue/next-LDG overlap;
// (2) fragment-row permutation m<8 -> s=2m, m>=8 -> s=2(m-8)+1 makes each
// thread's A needs a contiguous s-pair -> LDG.64 (half the LDG issues, perfect
// sectors); (3) B stored as interleaved (hi,lo) u64 -> LDS.64 (half the LDS
// issues). Arithmetic unchanged.

#define BATCH 64
#define ISZ   64
#define SEQ   4096
#define ESZ   64
#define MTILE 256        // s per tile
#define THREADS 256
#define NTILES (BATCH * (SEQ / MTILE))   // 1024
#define GRID_CTAS 296                    // 2 per SM x 148 SMs

#define BHL_STRIDE 68    // u64 per k2-row (64 + 4 pad)

typedef unsigned long long u64;

__device__ __forceinline__ uint32_t pack_h2(float a, float b) {
    __half2 h = __floats2half2_rn(a, b);   // .x -> low 16 bits
    uint32_t u; memcpy(&u, &h, 4);
    return u;
}

__device__ __forceinline__ void split_pair_h(float xa, float xb,
                                             uint32_t& hi, uint32_t& lo) {
    hi = pack_h2(xa, xb);
    __half2 hv; memcpy(&hv, &hi, 4);
    lo = pack_h2(xa - __half2float(hv.x), xb - __half2float(hv.y));
}

#define MMA_F16(d, a0, a1, a2, a3, b0, b1) \
    asm volatile("mma.sync.aligned.m16n8k16.row.col.f32.f16.f16.f32 " \
        "{%0,%1,%2,%3}, {%4,%5,%6,%7}, {%8,%9}, {%0,%1,%2,%3};" \
        : "+f"((d)[0]), "+f"((d)[1]), "+f"((d)[2]), "+f"((d)[3]) \
        : "r"(a0), "r"(a1), "r"(a2), "r"(a3), "r"(b0), "r"(b1))

__global__ __launch_bounds__(THREADS, 2)
void embed_mma_kernel(const float* __restrict__ in,
                      const float* __restrict__ emb,
                      float* __restrict__ out)
{
    // B (hi,lo) interleaved: Bhl[k2][e] = u64(hi_u32 | lo_u32<<32)
    __shared__ u64 Bhl[32 * BHL_STRIDE];   // 17408 B

    const int t = threadIdx.x;

    // ---- stage B once per CTA ----
    {
        #pragma unroll
        for (int j = 0; j < 8; ++j) {
            int idx = j * THREADS + t;      // 0..2047
            int k2 = idx >> 6, e = idx & 63;
            float x0 = emb[(2 * k2) * ESZ + e];
            float x1 = emb[(2 * k2 + 1) * ESZ + e];
            uint32_t hp, lp;
            split_pair_h(x0, x1, hp, lp);
            Bhl[k2 * BHL_STRIDE + e] = (u64)hp | ((u64)lp << 32);
        }
    }
    __syncthreads();

    const int w    = t >> 5;
    const int lane = t & 31;
    const int r  = lane >> 2;     // 0..7
    const int cq = lane & 3;      // 0..3

    // ---- persistent tile loop ----
    for (int tile = blockIdx.x; tile < NTILES; tile += GRID_CTAS) {
        const int b     = tile >> 4;
        const int stile = tile & 15;
        const int s0    = stile * MTILE;

        // warp covers s in [s0+32w, +32); m-tile mt at +16*mt.
        // fragment row m <-> s = sb + 2*(m&7) + (m>>3); thread (r,cq) loads
        // the contiguous pair s = sb+2r, sb+2r+1 per k-row -> float2 LDG.
        const float* Ab = in + (size_t)b * (ISZ * SEQ) + s0 + 32 * w + 2 * r;

        float acc[2][8][4];
        #pragma unroll
        for (int mt = 0; mt < 2; ++mt)
            #pragma unroll
            for (int nt = 0; nt < 8; ++nt)
                #pragma unroll
                for (int q = 0; q < 4; ++q) acc[mt][nt][q] = 0.0f;

        #pragma unroll
        for (int ks = 0; ks < 4; ++ks) {
            const int ka = ks * 16 + 2 * cq;

            // ---- A: 8 x LDG.64, both m-tiles ----
            uint32_t a0[2], a1[2], a2[2], a3[2];
            #pragma unroll
            for (int mt = 0; mt < 2; ++mt) {
                const float* p = Ab + 16 * mt;
                const float2 f0 = *reinterpret_cast<const float2*>(p + (size_t)(ka    ) * SEQ);
                const float2 f1 = *reinterpret_cast<const float2*>(p + (size_t)(ka + 1) * SEQ);
                const float2 f8 = *reinterpret_cast<const float2*>(p + (size_t)(ka + 8) * SEQ);
                const float2 f9 = *reinterpret_cast<const float2*>(p + (size_t)(ka + 9) * SEQ);
                a0[mt] = pack_h2(f0.x, f1.x);   // m=r,   k=2cq,2cq+1
                a1[mt] = pack_h2(f0.y, f1.y);   // m=r+8, k=2cq,2cq+1
                a2[mt] = pack_h2(f8.x, f9.x);   // m=r,   k=2cq+8,2cq+9
                a3[mt] = pack_h2(f8.y, f9.y);   // m=r+8, k=2cq+8,2cq+9
            }

            // ---- B fragments: 2 x LDS.64 per nt ----
            const u64* B0 = Bhl + (ks * 8 + cq) * BHL_STRIDE + r;
            const u64* B1 = Bhl + (ks * 8 + cq + 4) * BHL_STRIDE + r;

            #pragma unroll
            for (int nt = 0; nt < 8; ++nt) {
                const u64 v0 = B0[nt * 8];
                const u64 v1 = B1[nt * 8];
                const uint32_t b0h = (uint32_t)v0;
                const uint32_t b0l = (uint32_t)(v0 >> 32);
                const uint32_t b1h = (uint32_t)v1;
                const uint32_t b1l = (uint32_t)(v1 >> 32);
                MMA_F16(acc[0][nt], a0[0], a1[0], a2[0], a3[0], b0h, b1h);
                MMA_F16(acc[0][nt], a0[0], a1[0], a2[0], a3[0], b0l, b1l);
                MMA_F16(acc[1][nt], a0[1], a1[1], a2[1], a3[1], b0h, b1h);
                MMA_F16(acc[1][nt], a0[1], a1[1], a2[1], a3[1], b0l, b1l);
            }
        }

        // ---- epilogue: c0,c1 -> s = sb+2r ; c2,c3 -> s = sb+2r+1 ----
        #pragma unroll
        for (int mt = 0; mt < 2; ++mt) {
            const size_t srow = (size_t)b * SEQ + s0 + 32 * w + 16 * mt + 2 * r;
            float* orow0 = out + srow * ESZ;
            float* orow1 = out + (srow + 1) * ESZ;
            #pragma unroll
            for (int nt = 0; nt < 8; ++nt) {
                *reinterpret_cast<float2*>(orow0 + nt * 8 + 2 * cq) =
                    make_float2(acc[mt][nt][0], acc[mt][nt][1]);
                *reinterpret_cast<float2*>(orow1 + nt * 8 + 2 * cq) =
                    make_float2(acc[mt][nt][2], acc[mt][nt][3]);
            }
        }
    }
}

extern "C" void kernel_launch(void* const* d_in, const int* in_sizes, int n_in,
                              void* d_out, int out_size)
{
    const float* in  = (const float*)d_in[0];   // [64, 64, 4096]
    const float* emb = (const float*)d_in[1];   // [64, 64]
    float* out = (float*)d_out;                 // [64, 4096, 64]

    embed_mma_kernel<<<GRID_CTAS, THREADS>>>(in, emb, out);
}

// round 16
// speedup vs baseline: 1.0981x; 1.0981x over previous
#include <cuda_runtime.h>
#include <cuda_fp16.h>
#include <cstdint>
#include <cstring>

// einsum('bis,ie->bse') via mma.sync f16 2-term split.
//   inputs    [B=64, I=64, S=4096] f32
//   embedding [I=64, E=64]         f32
//   out       [B=64, S=4096, E=64] f32
//
// D = Ahi*Bhi + Ahi*Blo (f16 operands, fp32 accumulate), rel_err ~1.64e-4.
//
// vs round 12 (best 32.7us kernel): two issue-count cuts, tested WITHOUT the
// round-13 persistence change that regressed:
//  (1) fragment-row/s permutation m<8 -> s=2m, m>=8 -> s=2(m-8)+1 makes each
//      thread's per-k-row A needs a contiguous pair -> 8x LDG.64 per ks
//      (was 16x LDG.32); epilogue writes the matching permuted rows.
//  (2) B stored (hi,lo)-interleaved u64 -> 16x LDS.64 per ks (was 32x LDS.32).
// Arithmetic identical to round 12.

#define BATCH 64
#define ISZ   64
#define SEQ   4096
#define ESZ   64
#define MTILE 256        // s per CTA
#define THREADS 256

#define BHL_STRIDE 68    // u64 per k2-row (64 + 4 pad)
#define SMEM_TOTAL (32 * BHL_STRIDE * 8)   // 17408 B

typedef unsigned long long u64;

__device__ __forceinline__ uint32_t pack_h2(float a, float b) {
    __half2 h = __floats2half2_rn(a, b);   // .x -> low 16 bits
    uint32_t u; memcpy(&u, &h, 4);
    return u;
}

__device__ __forceinline__ void split_pair_h(float xa, float xb,
                                             uint32_t& hi, uint32_t& lo) {
    hi = pack_h2(xa, xb);
    __half2 hv; memcpy(&hv, &hi, 4);
    lo = pack_h2(xa - __half2float(hv.x), xb - __half2float(hv.y));
}

#define MMA_F16(d, a0, a1, a2, a3, b0, b1) \
    asm volatile("mma.sync.aligned.m16n8k16.row.col.f32.f16.f16.f32 " \
        "{%0,%1,%2,%3}, {%4,%5,%6,%7}, {%8,%9}, {%0,%1,%2,%3};" \
        : "+f"((d)[0]), "+f"((d)[1]), "+f"((d)[2]), "+f"((d)[3]) \
        : "r"(a0), "r"(a1), "r"(a2), "r"(a3), "r"(b0), "r"(b1))

__global__ __launch_bounds__(THREADS, 2)
void embed_mma_kernel(const float* __restrict__ in,
                      const float* __restrict__ emb,
                      float* __restrict__ out)
{
    // B (hi,lo) interleaved: Bhl[k2][e] = u64(hi | lo<<32)
    __shared__ u64 Bhl[32 * BHL_STRIDE];

    const int t = threadIdx.x;
    const int b     = blockIdx.x >> 4;      // 16 s-tiles per batch
    const int stile = blockIdx.x & 15;
    const int s0    = stile * MTILE;

    // ---- stage B: split f16 hi/lo, pack k-pairs, interleave ----
    {
        #pragma unroll
        for (int j = 0; j < 8; ++j) {
            int idx = j * THREADS + t;      // 0..2047
            int k2 = idx >> 6, e = idx & 63;
            float x0 = emb[(2 * k2) * ESZ + e];
            float x1 = emb[(2 * k2 + 1) * ESZ + e];
            uint32_t hp, lp;
            split_pair_h(x0, x1, hp, lp);
            Bhl[k2 * BHL_STRIDE + e] = (u64)hp | ((u64)lp << 32);
        }
    }
    __syncthreads();

    const int w    = t >> 5;
    const int lane = t & 31;
    const int r  = lane >> 2;     // 0..7
    const int cq = lane & 3;      // 0..3

    // warp covers s in [s0+32w, +32); m-tile mt at +16*mt.
    // fragment row m <-> s = sb + 2*(m&7) + (m>>3): thread (r,cq) loads the
    // contiguous pair s = sb+2r, sb+2r+1 per k-row -> LDG.64.
    const float* Ab = in + (size_t)b * (ISZ * SEQ) + s0 + 32 * w + 2 * r;

    float acc[2][8][4];
    #pragma unroll
    for (int mt = 0; mt < 2; ++mt)
        #pragma unroll
        for (int nt = 0; nt < 8; ++nt)
            #pragma unroll
            for (int q = 0; q < 4; ++q) acc[mt][nt][q] = 0.0f;

    #pragma unroll
    for (int ks = 0; ks < 4; ++ks) {
        const int ka = ks * 16 + 2 * cq;

        // ---- A: 8 x LDG.64 (both m-tiles), batched for MLP ----
        const float* p0 = Ab;
        const float* p1 = Ab + 16;
        const float2 f0a = *reinterpret_cast<const float2*>(p0 + (size_t)(ka    ) * SEQ);
        const float2 f1a = *reinterpret_cast<const float2*>(p0 + (size_t)(ka + 1) * SEQ);
        const float2 f8a = *reinterpret_cast<const float2*>(p0 + (size_t)(ka + 8) * SEQ);
        const float2 f9a = *reinterpret_cast<const float2*>(p0 + (size_t)(ka + 9) * SEQ);
        const float2 f0b = *reinterpret_cast<const float2*>(p1 + (size_t)(ka    ) * SEQ);
        const float2 f1b = *reinterpret_cast<const float2*>(p1 + (size_t)(ka + 1) * SEQ);
        const float2 f8b = *reinterpret_cast<const float2*>(p1 + (size_t)(ka + 8) * SEQ);
        const float2 f9b = *reinterpret_cast<const float2*>(p1 + (size_t)(ka + 9) * SEQ);

        uint32_t a0[2], a1[2], a2[2], a3[2];
        a0[0] = pack_h2(f0a.x, f1a.x);   // m=r   (s=sb+2r),   k=ka,ka+1
        a1[0] = pack_h2(f0a.y, f1a.y);   // m=r+8 (s=sb+2r+1), k=ka,ka+1
        a2[0] = pack_h2(f8a.x, f9a.x);   // m=r,   k=ka+8,ka+9
        a3[0] = pack_h2(f8a.y, f9a.y);   // m=r+8, k=ka+8,ka+9
        a0[1] = pack_h2(f0b.x, f1b.x);
        a1[1] = pack_h2(f0b.y, f1b.y);
        a2[1] = pack_h2(f8b.x, f9b.x);
        a3[1] = pack_h2(f8b.y, f9b.y);

        // ---- B fragments: 2 x LDS.64 per nt ----
        const u64* B0 = Bhl + (ks * 8 + cq) * BHL_STRIDE + r;
        const u64* B1 = Bhl + (ks * 8 + cq + 4) * BHL_STRIDE + r;

        #pragma unroll
        for (int nt = 0; nt < 8; ++nt) {
            const u64 v0 = B0[nt * 8];
            const u64 v1 = B1[nt * 8];
            const uint32_t b0h = (uint32_t)v0;
            const uint32_t b0l = (uint32_t)(v0 >> 32);
            const uint32_t b1h = (uint32_t)v1;
            const uint32_t b1l = (uint32_t)(v1 >> 32);
            MMA_F16(acc[0][nt], a0[0], a1[0], a2[0], a3[0], b0h, b1h);
            MMA_F16(acc[0][nt], a0[0], a1[0], a2[0], a3[0], b0l, b1l);
            MMA_F16(acc[1][nt], a0[1], a1[1], a2[1], a3[1], b0h, b1h);
            MMA_F16(acc[1][nt], a0[1], a1[1], a2[1], a3[1], b0l, b1l);
        }
    }

    // ---- epilogue: c0,c1 -> s = sb+2r ; c2,c3 -> s = sb+2r+1 ----
    #pragma unroll
    for (int mt = 0; mt < 2; ++mt) {
        const size_t srow = (size_t)b * SEQ + s0 + 32 * w + 16 * mt + 2 * r;
        float* orow0 = out + srow * ESZ;
        float* orow1 = out + (srow + 1) * ESZ;
        #pragma unroll
        for (int nt = 0; nt < 8; ++nt) {
            *reinterpret_cast<float2*>(orow0 + nt * 8 + 2 * cq) =
                make_float2(acc[mt][nt][0], acc[mt][nt][1]);
            *reinterpret_cast<float2*>(orow1 + nt * 8 + 2 * cq) =
                make_float2(acc[mt][nt][2], acc[mt][nt][3]);
        }
    }
}

extern "C" void kernel_launch(void* const* d_in, const int* in_sizes, int n_in,
                              void* d_out, int out_size)
{
    const float* in  = (const float*)d_in[0];   // [64, 64, 4096]
    const float* emb = (const float*)d_in[1];   // [64, 64]
    float* out = (float*)d_out;                 // [64, 4096, 64]

    const int blocks = BATCH * (SEQ / MTILE);   // 1024
    embed_mma_kernel<<<blocks, THREADS, SMEM_TOTAL>>>(in, emb, out);
}

// round 17
// speedup vs baseline: 1.1647x; 1.0607x over previous
#include <cuda_runtime.h>
#include <cuda_fp16.h>
#include <cstdint>
#include <cstring>

// einsum('bis,ie->bse') via mma.sync f16 2-term split.
//   inputs    [B=64, I=64, S=4096] f32
//   embedding [I=64, E=64]         f32
//   out       [B=64, S=4096, E=64] f32
//
// D = Ahi*Bhi + Ahi*Blo (f16 operands, fp32 accumulate), rel_err ~1.64e-4.
//
// vs round 16 (best 32.06us kernel): two more width halvings, arithmetic
// unchanged:
//  (1) 4-way s-permutation (mt0,r)->4r, (mt0,r+8)->4r+1, (mt1,r)->4r+2,
//      (mt1,r+8)->4r+3: one LDG.128 per k-row feeds all four fragment slots
//      -> 4 LDG.128 per ks (was 8 LDG.64); 16 dense sectors per instruction.
//  (2) B stored transposed-within-row (slot = r*8+nt, stride 66 u64): each
//      thread's 8 nt-values are contiguous -> 8 LDS.128 per ks (was 16
//      LDS.64); phase bank pattern cq*4+r*16 mod 32 = conflict-free.

#define BATCH 64
#define ISZ   64
#define SEQ   4096
#define ESZ   64
#define MTILE 256        // s per CTA
#define THREADS 256

#define BHL_STRIDE 66    // u64 per k2-row: 528B -> 16B-phase banks cq*4+r*16, all distinct
#define SMEM_TOTAL (32 * BHL_STRIDE * 8)   // 16896 B

typedef unsigned long long u64;

__device__ __forceinline__ uint32_t pack_h2(float a, float b) {
    __half2 h = __floats2half2_rn(a, b);   // .x -> low 16 bits
    uint32_t u; memcpy(&u, &h, 4);
    return u;
}

__device__ __forceinline__ void split_pair_h(float xa, float xb,
                                             uint32_t& hi, uint32_t& lo) {
    hi = pack_h2(xa, xb);
    __half2 hv; memcpy(&hv, &hi, 4);
    lo = pack_h2(xa - __half2float(hv.x), xb - __half2float(hv.y));
}

#define MMA_F16(d, a0, a1, a2, a3, b0, b1) \
    asm volatile("mma.sync.aligned.m16n8k16.row.col.f32.f16.f16.f32 " \
        "{%0,%1,%2,%3}, {%4,%5,%6,%7}, {%8,%9}, {%0,%1,%2,%3};" \
        : "+f"((d)[0]), "+f"((d)[1]), "+f"((d)[2]), "+f"((d)[3]) \
        : "r"(a0), "r"(a1), "r"(a2), "r"(a3), "r"(b0), "r"(b1))

__global__ __launch_bounds__(THREADS, 2)
void embed_mma_kernel(const float* __restrict__ in,
                      const float* __restrict__ emb,
                      float* __restrict__ out)
{
    // B (hi,lo)-interleaved u64, transposed within each k2-row:
    // Bhl[k2][r*8 + nt] = pack(emb[2k2][nt*8+r], emb[2k2+1][nt*8+r])
    __shared__ u64 Bhl[32 * BHL_STRIDE];

    const int t = threadIdx.x;
    const int b     = blockIdx.x >> 4;      // 16 s-tiles per batch
    const int stile = blockIdx.x & 15;
    const int s0    = stile * MTILE;

    // ---- stage B: split f16 hi/lo, pack k-pairs, transpose-in-row ----
    {
        #pragma unroll
        for (int j = 0; j < 8; ++j) {
            int idx  = j * THREADS + t;      // 0..2047
            int k2   = idx >> 6;
            int slot = idx & 63;             // r*8 + nt
            int rr   = slot >> 3;
            int nt   = slot & 7;
            int e    = nt * 8 + rr;
            float x0 = emb[(2 * k2) * ESZ + e];
            float x1 = emb[(2 * k2 + 1) * ESZ + e];
            uint32_t hp, lp;
            split_pair_h(x0, x1, hp, lp);
            Bhl[k2 * BHL_STRIDE + slot] = (u64)hp | ((u64)lp << 32);
        }
    }
    __syncthreads();

    const int w    = t >> 5;
    const int lane = t & 31;
    const int r  = lane >> 2;     // 0..7
    const int cq = lane & 3;      // 0..3

    // warp covers s in [s0+32w, +32).
    // fragment slot <-> s: (mt0, m=r)->4r, (mt0, m=r+8)->4r+1,
    //                      (mt1, m=r)->4r+2, (mt1, m=r+8)->4r+3
    const float* Ab = in + (size_t)b * (ISZ * SEQ) + s0 + 32 * w + 4 * r;

    float acc[2][8][4];
    #pragma unroll
    for (int mt = 0; mt < 2; ++mt)
        #pragma unroll
        for (int nt = 0; nt < 8; ++nt)
            #pragma unroll
            for (int q = 0; q < 4; ++q) acc[mt][nt][q] = 0.0f;

    #pragma unroll
    for (int ks = 0; ks < 4; ++ks) {
        const int ka = ks * 16 + 2 * cq;

        // ---- A: 4 x LDG.128 (k-rows ka, ka+1, ka+8, ka+9) ----
        const float4 f0 = *reinterpret_cast<const float4*>(Ab + (size_t)(ka    ) * SEQ);
        const float4 f1 = *reinterpret_cast<const float4*>(Ab + (size_t)(ka + 1) * SEQ);
        const float4 f8 = *reinterpret_cast<const float4*>(Ab + (size_t)(ka + 8) * SEQ);
        const float4 f9 = *reinterpret_cast<const float4*>(Ab + (size_t)(ka + 9) * SEQ);

        uint32_t a0[2], a1[2], a2[2], a3[2];
        a0[0] = pack_h2(f0.x, f1.x);   // mt0, m=r,   k=ka,ka+1
        a1[0] = pack_h2(f0.y, f1.y);   // mt0, m=r+8
        a0[1] = pack_h2(f0.z, f1.z);   // mt1, m=r
        a1[1] = pack_h2(f0.w, f1.w);   // mt1, m=r+8
        a2[0] = pack_h2(f8.x, f9.x);   // mt0, m=r,   k=ka+8,ka+9
        a3[0] = pack_h2(f8.y, f9.y);
        a2[1] = pack_h2(f8.z, f9.z);
        a3[1] = pack_h2(f8.w, f9.w);

        // ---- B fragments: 8 x LDS.128 (contiguous nt-slots) ----
        const u64* B0p = Bhl + (ks * 8 + cq) * BHL_STRIDE + r * 8;
        const u64* B1p = B0p + 4 * BHL_STRIDE;
        u64 b0[8], b1[8];
        #pragma unroll
        for (int j = 0; j < 4; ++j) {
            ulonglong2 v0 = reinterpret_cast<const ulonglong2*>(B0p)[j];
            ulonglong2 v1 = reinterpret_cast<const ulonglong2*>(B1p)[j];
            b0[2 * j] = v0.x;  b0[2 * j + 1] = v0.y;
            b1[2 * j] = v1.x;  b1[2 * j + 1] = v1.y;
        }

        #pragma unroll
        for (int nt = 0; nt < 8; ++nt) {
            const uint32_t b0h = (uint32_t)b0[nt];
            const uint32_t b0l = (uint32_t)(b0[nt] >> 32);
            const uint32_t b1h = (uint32_t)b1[nt];
            const uint32_t b1l = (uint32_t)(b1[nt] >> 32);
            MMA_F16(acc[0][nt], a0[0], a1[0], a2[0], a3[0], b0h, b1h);
            MMA_F16(acc[0][nt], a0[0], a1[0], a2[0], a3[0], b0l, b1l);
            MMA_F16(acc[1][nt], a0[1], a1[1], a2[1], a3[1], b0h, b1h);
            MMA_F16(acc[1][nt], a0[1], a1[1], a2[1], a3[1], b0l, b1l);
        }
    }

    // ---- epilogue: mt -> rows 4r+2mt (c0,c1) and 4r+2mt+1 (c2,c3) ----
    #pragma unroll
    for (int mt = 0; mt < 2; ++mt) {
        const size_t srow = (size_t)b * SEQ + s0 + 32 * w + 4 * r + 2 * mt;
        float* orow0 = out + srow * ESZ;
        float* orow1 = out + (srow + 1) * ESZ;
        #pragma unroll
        for (int nt = 0; nt < 8; ++nt) {
            *reinterpret_cast<float2*>(orow0 + nt * 8 + 2 * cq) =
                make_float2(acc[mt][nt][0], acc[mt][nt][1]);
            *reinterpret_cast<float2*>(orow1 + nt * 8 + 2 * cq) =
                make_float2(acc[mt][nt][2], acc[mt][nt][3]);
        }
    }
}

extern "C" void kernel_launch(void* const* d_in, const int* in_sizes, int n_in,
                              void* d_out, int out_size)
{
    const float* in  = (const float*)d_in[0];   // [64, 64, 4096]
    const float* emb = (const float*)d_in[1];   // [64, 64]
    float* out = (float*)d_out;                 // [64, 4096, 64]

    const int blocks = BATCH * (SEQ / MTILE);   // 1024
    embed_mma_kernel<<<blocks, THREADS, SMEM_TOTAL>>>(in, emb, out);
}